// round 12
// baseline (speedup 1.0000x reference)
#include <cuda_runtime.h>
#include <cuda_bf16.h>

// Problem constants
#define B_    8
#define H_    256
#define P_    225
#define KER_  32
#define HALF_ 16
#define K_    2
#define CDA_  64
#define NBC_  16
#define NRB_  15
#define NCH_  8
#define NPART_ (NRB_ * NCH_)
#define GRID_ 512

// Output section offsets (floats)
#define OFF_CLS   0
#define OFF_FEAT  65536
#define OFF_VALS  2162688
#define OFF_PES   2162720
#define OFF_TRUE  2195488
#define OFF_OXY   2228256

// Scratch — channel-0 maps only (p1 = 1 - p0 => pooled1 = 1 - pooled0)
__device__ float g_rowsum[B_ * H_ * P_];
__device__ float g_pooled[B_ * P_ * P_];
__device__ float g_cval0[B_ * NPART_];
__device__ int   g_cidx0[B_ * NPART_];
__device__ float g_cval1[B_ * NPART_];
__device__ int   g_cidx1[B_ * NPART_];
__device__ int   g_selpx[NBC_ * K_];
__device__ int   g_selpy[NBC_ * K_];

// Per-map sync. Counters self-reset; release counters are MONOTONE
// (waiters compare against an entry snapshot) -> safe across graph replays.
__device__ unsigned g_rs_cnt[B_];     // rowsum arrivals (reset by 64th)
__device__ unsigned g_rs_rel[B_];     // rowsum release (monotone)
__device__ unsigned g_tick[B_];       // pool ticket (reset by selection blk)
__device__ unsigned g_sel_rel[B_];    // selection release (monotone)

__device__ __forceinline__ void warp_argmax(float& bv, int& bix) {
#pragma unroll
    for (int o = 16; o > 0; o >>= 1) {
        float ov = __shfl_xor_sync(0xffffffffu, bv, o);
        int   oi = __shfl_xor_sync(0xffffffffu, bix, o);
        if (ov > bv || (ov == bv && oi < bix)) { bv = ov; bix = oi; }
    }
}

__device__ __forceinline__ void decode_patch(
    int p, const float* infeat, const float* pesudo, const float* labelT,
    const float* feat, const float*& src, int& sel, int& map, long& base)
{
    int Csrc, ch, c, j, b;
    if (p < 64) {
        int t = p;
        ch = t & 1;  t >>= 1;
        b  = t & 7;  t >>= 3;
        j  = t & 1;  t >>= 1;
        c  = t;
        src = infeat; Csrc = 2;
        base = OFF_CLS + (long)p * 1024;
    } else if (p < 2112) {
        int t = p - 64;
        int local = t;
        ch = t & 63; t >>= 6;
        b  = t & 7;  t >>= 3;
        j  = t & 1;  t >>= 1;
        c  = t;
        src = feat; Csrc = CDA_;
        base = OFF_FEAT + (long)local * 1024;
    } else if (p < 2144) {
        int t = p - 2112;
        int local = t;
        ch = 0;
        b  = t & 7;  t >>= 3;
        j  = t & 1;  t >>= 1;
        c  = t;
        src = pesudo; Csrc = 1;
        base = OFF_PES + (long)local * 1024;
    } else {
        int t = p - 2144;
        int local = t;
        ch = 0;
        b  = t & 7;  t >>= 3;
        j  = t & 1;  t >>= 1;
        c  = t;
        src = labelT; Csrc = 1;
        base = OFF_TRUE + (long)local * 1024;
    }
    sel = (b * 2 + c) * K_ + j;
    map = b;
    src += ((long)b * Csrc + ch) * H_ * H_;
}

// ===========================================================================
// Single pipelined kernel. grid 512, 256 thr, all blocks co-resident.
// ===========================================================================
__global__ void __launch_bounds__(256, 4)
k_all(const float* __restrict__ infeat,
      const float* __restrict__ pesudo,
      const float* __restrict__ labelT,
      const float* __restrict__ feat,
      float* __restrict__ out) {
    __shared__ float sc[4][H_];
    __shared__ float sv[256];
    __shared__ int   si[256];
    __shared__ unsigned s_rssnap[B_];
    __shared__ unsigned s_selsnap[B_];
    __shared__ unsigned s_isLast;

    const int tid  = threadIdx.x;
    const int lane = tid & 31;
    const int blk  = blockIdx.x;

    // ---- entry snapshots (FIRST thing; pre-release by co-residency) ----
    if (tid < B_) {
        s_rssnap[tid]  = *(volatile unsigned*)&g_rs_rel[tid];
        s_selsnap[tid] = *(volatile unsigned*)&g_sel_rel[tid];
    }
    __syncthreads();

    // ================= Phase A: rowsum (one 4-row task per block) ==========
    {
        const int g0 = blk * 4;
        const int b  = g0 >> 8;
        const int y0 = g0 & 255;
        const int x  = tid;

        const float* c0 = infeat + ((long)(b * 2 + 0) * H_ + y0) * H_ + x;
        const float* c1 = infeat + ((long)(b * 2 + 1) * H_ + y0) * H_ + x;

        float a0[4], a1[4];
#pragma unroll
        for (int r = 0; r < 4; r++) a0[r] = c0[r * H_];
#pragma unroll
        for (int r = 0; r < 4; r++) a1[r] = c1[r * H_];

        float s[4];
#pragma unroll
        for (int r = 0; r < 4; r++) s[r] = 1.0f / (1.0f + __expf(a1[r] - a0[r]));

#pragma unroll
        for (int o = 1; o < 32; o <<= 1) {
#pragma unroll
            for (int r = 0; r < 4; r++) {
                float t = __shfl_up_sync(0xffffffffu, s[r], o);
                if (lane >= o) s[r] += t;
            }
        }
#pragma unroll
        for (int r = 0; r < 4; r++) sc[r][x] = s[r];
        __syncthreads();

        if (x < P_) {
            int w = x >> 5, rr = x & 31;
#pragma unroll
            for (int r = 0; r < 4; r++) {
                float S = sc[r][(w << 5) | 31];
                float win = (rr == 0) ? S : (S - sc[r][x - 1]) + sc[r][x + 31];
                g_rowsum[((long)b * H_ + y0 + r) * P_ + x] = win;
            }
        }

        // arrive; 64th arriver releases the map
        __threadfence();
        __syncthreads();
        if (tid == 0) {
            unsigned my = atomicAdd(&g_rs_cnt[b], 1u);
            if (my == 63u) {
                atomicExch(&g_rs_cnt[b], 0u);     // reset for next replay
                __threadfence();
                atomicAdd(&g_rs_rel[b], 1u);      // release (monotone)
            }
        }
    }

    // ============ Phase B+C: pool slab + selection (blocks 0..119) ==========
    if (blk < B_ * NRB_) {
        const int m    = blk / NRB_;
        const int slab = blk % NRB_;
        const int y0   = slab * 15;

        // wait for map m rowsums
        if (tid == 0) {
            volatile unsigned* vr = (volatile unsigned*)&g_rs_rel[m];
            unsigned snap = s_rssnap[m];
            while (*vr == snap) __nanosleep(32);
        }
        __syncthreads();
        __threadfence();

        const float* rs = g_rowsum + m * H_ * P_;
        float* outp = g_pooled + m * P_ * P_;

        float best0 = -1e30f, best1 = -1e30f;
        int bi0 = 0x7fffffff, bi1 = 0x7fffffff;

        if (tid < P_) {
            float s = 0.0f;
#pragma unroll
            for (int i = 0; i < KER_; i++) s += rs[(y0 + i) * P_ + tid];
            float v = s * (1.0f / 1024.0f);
            outp[y0 * P_ + tid] = v;
            best0 = v; bi0 = y0 * P_ + tid;
            best1 = 1.0f - v; bi1 = bi0;
#pragma unroll
            for (int q = 1; q < 15; q++) {
                int py = y0 + q;
                s += rs[(py + 31) * P_ + tid] - rs[(py - 1) * P_ + tid];
                v = s * (1.0f / 1024.0f);
                outp[py * P_ + tid] = v;
                int idx = py * P_ + tid;
                if (v > best0) { best0 = v; bi0 = idx; }
                float w = 1.0f - v;
                if (w > best1) { best1 = w; bi1 = idx; }
            }
        }
        {
            const int warp = tid >> 5;
            warp_argmax(best0, bi0);
            warp_argmax(best1, bi1);
            if (lane == 0) {
                int o = (m * NRB_ + slab) * NCH_ + warp;
                g_cval0[o] = best0; g_cidx0[o] = bi0;
                g_cval1[o] = best1; g_cidx1[o] = bi1;
            }
        }

        __threadfence();
        __syncthreads();
        if (tid == 0) {
            unsigned t = atomicAdd(&g_tick[m], 1u);
            s_isLast = (t == NRB_ - 1) ? 1u : 0u;
        }
        __syncthreads();

        if (s_isLast) {
            __threadfence();
            const int half = tid >> 7;
            const int h    = tid & 127;
            const int bc   = m * 2 + half;
            const float* pm = g_pooled + m * P_ * P_;
            const float* cval = half ? g_cval1 : g_cval0;
            const int*   cidx = half ? g_cidx1 : g_cidx0;

            // pass 1: reduce 120 partials (per half)
            float best = -1e30f;
            int bi = 0x7fffffff;
            if (h < NPART_) {
                best = cval[m * NPART_ + h];
                bi   = cidx[m * NPART_ + h];
            }
            sv[tid] = best; si[tid] = bi;
            __syncthreads();
            for (int s = 64; s > 0; s >>= 1) {
                if (h < s) {
                    float ov = sv[tid + s];
                    int   oi = si[tid + s];
                    if (ov > sv[tid] || (ov == sv[tid] && oi < si[tid])) {
                        sv[tid] = ov; si[tid] = oi;
                    }
                }
                __syncthreads();
            }
            int idx0 = si[half << 7];
            float val0 = sv[half << 7];
            int py0 = idx0 / P_;
            int px0 = idx0 - py0 * P_;
            __syncthreads();

            // pass 2: untouched partials + batched rescan of touched cells
            int lo  = max(0, py0 - HALF_), hi  = min(P_, py0 + HALF_);
            int clo = max(0, px0 - HALF_), chi = min(P_, px0 + HALF_);
            int rblo = lo / 15, rbhi = (hi - 1) / 15;
            int cblo = clo / 32, cbhi = (chi - 1) / 32;

            best = -1e30f; bi = 0x7fffffff;
            if (h < NPART_) {
                int sb = h >> 3, cb = h & 7;
                if (sb < rblo || sb > rbhi || cb < cblo || cb > cbhi) {
                    best = cval[m * NPART_ + h];
                    bi   = cidx[m * NPART_ + h];
                }
            }
            int r0 = rblo * 15, r1 = min(P_, (rbhi + 1) * 15);
            int c0 = cblo * 32, c1 = min(P_, (cbhi + 1) * 32);
            int W = c1 - c0;
            int n = (r1 - r0) * W;
            for (int i0 = h; i0 < n; i0 += 128 * 8) {
#pragma unroll
                for (int u = 0; u < 8; u++) {
                    int i = i0 + u * 128;
                    if (i < n) {
                        int rr = i / W;
                        int col = c0 + (i - rr * W);
                        int row = r0 + rr;
                        int idx = row * P_ + col;
                        float v = pm[idx];
                        if (half) v = 1.0f - v;
                        if (row >= lo && row < hi && col >= clo && col < chi) v = 0.0f;
                        if (v > best || (v == best && idx < bi)) { best = v; bi = idx; }
                    }
                }
            }
            sv[tid] = best; si[tid] = bi;
            __syncthreads();
            for (int s = 64; s > 0; s >>= 1) {
                if (h < s) {
                    float ov = sv[tid + s];
                    int   oi = si[tid + s];
                    if (ov > sv[tid] || (ov == sv[tid] && oi < si[tid])) {
                        sv[tid] = ov; si[tid] = oi;
                    }
                }
                __syncthreads();
            }

            if (h == 0) {
                int idx1 = si[half << 7];
                float val1 = sv[half << 7];
                int py1 = idx1 / P_;
                int px1 = idx1 - py1 * P_;

                int pxs[K_] = {px0, px1};
                int pys[K_] = {py0, py1};
                float vals[K_] = {val0, val1};
                int c = half, b = m;
#pragma unroll
                for (int j = 0; j < K_; j++) {
                    g_selpx[bc * K_ + j] = pxs[j];
                    g_selpy[bc * K_ + j] = pys[j];
                    out[OFF_VALS + (c * K_ + j) * B_ + b] = vals[j];
                    int o = OFF_OXY + ((c * K_ + j) * B_ + b) * 4;
                    out[o + 0] = (float)pxs[j];
                    out[o + 1] = (float)(pxs[j] + KER_ - 1);
                    out[o + 2] = (float)pys[j];
                    out[o + 3] = (float)(pys[j] + KER_ - 1);
                }
            }
            // release selections for this map
            __threadfence();
            __syncthreads();
            if (tid == 0) {
                g_tick[m] = 0;                 // reset ticket for next replay
                __threadfence();
                atomicAdd(&g_sel_rel[m], 1u);  // release (monotone)
            }
        }
    }

    // ============ Phase D: extract (grid-stride over 1088 patch pairs) ======
    for (int task = blk; task < 1088; task += GRID_) {
        int p0 = task * 2;
        int p1 = p0 + 1;

        const float *srcA, *srcB;
        int selA, mapA; long baseA;
        int selB, mapB; long baseB;
        decode_patch(p0, infeat, pesudo, labelT, feat, srcA, selA, mapA, baseA);
        decode_patch(p1, infeat, pesudo, labelT, feat, srcB, selB, mapB, baseB);

        // wait for both maps' selections
        if (tid == 0) {
            volatile unsigned* va = (volatile unsigned*)&g_sel_rel[mapA];
            unsigned sa = s_selsnap[mapA];
            while (*va == sa) __nanosleep(32);
            if (mapB != mapA) {
                volatile unsigned* vb = (volatile unsigned*)&g_sel_rel[mapB];
                unsigned sb = s_selsnap[mapB];
                while (*vb == sb) __nanosleep(32);
            }
        }
        __syncthreads();
        __threadfence();

        int pxA = g_selpx[selA], pyA = g_selpy[selA];
        int pxB = g_selpx[selB], pyB = g_selpy[selB];

        int dy = tid >> 3;
        int dx = (tid & 7) * 4;

        const float* sa = srcA + (pyA + dy) * H_ + pxA + dx;
        const float* sb = srcB + (pyB + dy) * H_ + pxB + dx;

        float4 va, vb;
        va.x = sa[0]; va.y = sa[1]; va.z = sa[2]; va.w = sa[3];
        vb.x = sb[0]; vb.y = sb[1]; vb.z = sb[2]; vb.w = sb[3];

        *reinterpret_cast<float4*>(out + baseA + (long)tid * 4) = va;
        *reinterpret_cast<float4*>(out + baseB + (long)tid * 4) = vb;
    }
}

// ---------------------------------------------------------------------------
extern "C" void kernel_launch(void* const* d_in, const int* in_sizes, int n_in,
                              void* d_out, int out_size) {
    const float* infeat  = (const float*)d_in[0];
    const float* pesudo  = (const float*)d_in[1];
    const float* labelT  = (const float*)d_in[2];
    const float* featDA  = (const float*)d_in[3];
    float* out = (float*)d_out;

    k_all<<<GRID_, 256>>>(infeat, pesudo, labelT, featDA, out);
}

// round 13
// speedup vs baseline: 1.1350x; 1.1350x over previous
#include <cuda_runtime.h>
#include <cuda_bf16.h>

// Problem constants
#define B_    8
#define H_    256
#define P_    225
#define KER_  32
#define HALF_ 16
#define K_    2
#define CDA_  64
#define NBC_  16
#define NRB_  15
#define NCH_  8
#define NPART_ (NRB_ * NCH_)

// Output section offsets (floats)
#define OFF_CLS   0
#define OFF_FEAT  65536
#define OFF_VALS  2162688
#define OFF_PES   2162720
#define OFF_TRUE  2195488
#define OFF_OXY   2228256

// Scratch — channel-0 maps only (p1 = 1 - p0 => pooled1 = 1 - pooled0)
__device__ float g_rowsum[B_ * H_ * P_];
__device__ float g_pooled[B_ * P_ * P_];
__device__ float g_cval0[B_ * NPART_];
__device__ int   g_cidx0[B_ * NPART_];
__device__ float g_cval1[B_ * NPART_];
__device__ int   g_cidx1[B_ * NPART_];
__device__ int   g_selpx[NBC_ * K_];
__device__ int   g_selpy[NBC_ * K_];
__device__ unsigned g_tick[B_];

__device__ __forceinline__ void warp_argmax(float& bv, int& bix) {
#pragma unroll
    for (int o = 16; o > 0; o >>= 1) {
        float ov = __shfl_xor_sync(0xffffffffu, bv, o);
        int   oi = __shfl_xor_sync(0xffffffffu, bix, o);
        if (ov > bv || (ov == bv && oi < bix)) { bv = ov; bix = oi; }
    }
}

// ===========================================================================
// K1: channel-0 softmax prob + horizontal 32-window sums (4 rows/block,
// MLP 8, ILP-4 scans). grid 512, 256 threads. Triggers PDL completion after
// its final fenced writes.
// ===========================================================================
__global__ void k_rowsum(const float* __restrict__ infeat) {
    const int blk = blockIdx.x;
    const int g0  = blk * 4;
    const int b   = g0 >> 8;
    const int y0  = g0 & 255;
    const int x   = threadIdx.x;
    const int lane = x & 31;

    __shared__ float sc[4][H_];

    const float* c0 = infeat + ((long)(b * 2 + 0) * H_ + y0) * H_ + x;
    const float* c1 = infeat + ((long)(b * 2 + 1) * H_ + y0) * H_ + x;

    float a0[4], a1[4];
#pragma unroll
    for (int r = 0; r < 4; r++) a0[r] = c0[r * H_];
#pragma unroll
    for (int r = 0; r < 4; r++) a1[r] = c1[r * H_];

    float s[4];
#pragma unroll
    for (int r = 0; r < 4; r++) s[r] = 1.0f / (1.0f + __expf(a1[r] - a0[r]));

#pragma unroll
    for (int o = 1; o < 32; o <<= 1) {
#pragma unroll
        for (int r = 0; r < 4; r++) {
            float t = __shfl_up_sync(0xffffffffu, s[r], o);
            if (lane >= o) s[r] += t;
        }
    }
#pragma unroll
    for (int r = 0; r < 4; r++) sc[r][x] = s[r];
    __syncthreads();

    if (x < P_) {
        int w = x >> 5, rr = x & 31;
#pragma unroll
        for (int r = 0; r < 4; r++) {
            float S = sc[r][(w << 5) | 31];
            float win = (rr == 0) ? S : (S - sc[r][x - 1]) + sc[r][x + 31];
            g_rowsum[((long)b * H_ + y0 + r) * P_ + x] = win;
        }
    }

    __threadfence();
    cudaTriggerProgrammaticLaunchCompletion();
}

// ===========================================================================
// K2 (PDL consumer of K1): vertical pooling + dual partials; per-map ticket
// -> last slab block runs BOTH channels' selections. grid (8,15), 256 thr.
// Triggers PDL completion after selection writes.
// ===========================================================================
__global__ void __launch_bounds__(256)
k_poolsel(float* __restrict__ out) {
    __shared__ float sv[256];
    __shared__ int   si[256];
    __shared__ unsigned s_isLast;

    cudaGridDependencySynchronize();   // wait for K1's g_rowsum

    const int tid  = threadIdx.x;
    const int lane = tid & 31;
    const int warp = tid >> 5;
    const int m    = blockIdx.x;
    const int slab = blockIdx.y;
    const int y0   = slab * 15;

    const float* rs = g_rowsum + m * H_ * P_;
    float* outp = g_pooled + m * P_ * P_;

    float best0 = -1e30f, best1 = -1e30f;
    int bi0 = 0x7fffffff, bi1 = 0x7fffffff;

    if (tid < P_) {
        float s = 0.0f;
#pragma unroll
        for (int i = 0; i < KER_; i++) s += rs[(y0 + i) * P_ + tid];
        float v = s * (1.0f / 1024.0f);
        outp[y0 * P_ + tid] = v;
        best0 = v; bi0 = y0 * P_ + tid;
        best1 = 1.0f - v; bi1 = bi0;
#pragma unroll
        for (int q = 1; q < 15; q++) {
            int py = y0 + q;
            s += rs[(py + 31) * P_ + tid] - rs[(py - 1) * P_ + tid];
            v = s * (1.0f / 1024.0f);
            outp[py * P_ + tid] = v;
            int idx = py * P_ + tid;
            if (v > best0) { best0 = v; bi0 = idx; }
            float w = 1.0f - v;
            if (w > best1) { best1 = w; bi1 = idx; }
        }
    }
    warp_argmax(best0, bi0);
    warp_argmax(best1, bi1);
    if (lane == 0) {
        int o = (m * NRB_ + slab) * NCH_ + warp;
        g_cval0[o] = best0; g_cidx0[o] = bi0;
        g_cval1[o] = best1; g_cidx1[o] = bi1;
    }

    __threadfence();
    __syncthreads();
    if (tid == 0) {
        unsigned t = atomicAdd(&g_tick[m], 1u);
        s_isLast = (t == NRB_ - 1) ? 1u : 0u;
    }
    __syncthreads();
    if (!s_isLast) return;             // exit counts as PDL trigger
    __threadfence();

    const int half = tid >> 7;
    const int h    = tid & 127;
    const int bc   = m * 2 + half;
    const int b    = m;
    const int c    = half;
    const float* pm = g_pooled + m * P_ * P_;
    const float* cval = half ? g_cval1 : g_cval0;
    const int*   cidx = half ? g_cidx1 : g_cidx0;

    // pass 1: reduce 120 partials (per half)
    float best = -1e30f;
    int bi = 0x7fffffff;
    if (h < NPART_) {
        best = cval[m * NPART_ + h];
        bi   = cidx[m * NPART_ + h];
    }
    sv[tid] = best; si[tid] = bi;
    __syncthreads();
    for (int s = 64; s > 0; s >>= 1) {
        if (h < s) {
            float ov = sv[tid + s];
            int   oi = si[tid + s];
            if (ov > sv[tid] || (ov == sv[tid] && oi < si[tid])) {
                sv[tid] = ov; si[tid] = oi;
            }
        }
        __syncthreads();
    }
    int idx0 = si[half << 7];
    float val0 = sv[half << 7];
    int py0 = idx0 / P_;
    int px0 = idx0 - py0 * P_;
    __syncthreads();

    // pass 2: untouched partials + MLP-batched rescan of touched cells
    int lo  = max(0, py0 - HALF_), hi  = min(P_, py0 + HALF_);
    int clo = max(0, px0 - HALF_), chi = min(P_, px0 + HALF_);
    int rblo = lo / 15, rbhi = (hi - 1) / 15;
    int cblo = clo / 32, cbhi = (chi - 1) / 32;

    best = -1e30f; bi = 0x7fffffff;
    if (h < NPART_) {
        int sb = h >> 3, cb = h & 7;
        if (sb < rblo || sb > rbhi || cb < cblo || cb > cbhi) {
            best = cval[m * NPART_ + h];
            bi   = cidx[m * NPART_ + h];
        }
    }
    int r0 = rblo * 15, r1 = min(P_, (rbhi + 1) * 15);
    int c0 = cblo * 32, c1 = min(P_, (cbhi + 1) * 32);
    int W = c1 - c0;
    int n = (r1 - r0) * W;
    for (int i0 = h; i0 < n; i0 += 128 * 8) {
#pragma unroll
        for (int u = 0; u < 8; u++) {
            int i = i0 + u * 128;
            if (i < n) {
                int rr = i / W;
                int col = c0 + (i - rr * W);
                int row = r0 + rr;
                int idx = row * P_ + col;
                float v = pm[idx];
                if (half) v = 1.0f - v;
                if (row >= lo && row < hi && col >= clo && col < chi) v = 0.0f;
                if (v > best || (v == best && idx < bi)) { best = v; bi = idx; }
            }
        }
    }
    sv[tid] = best; si[tid] = bi;
    __syncthreads();
    for (int s = 64; s > 0; s >>= 1) {
        if (h < s) {
            float ov = sv[tid + s];
            int   oi = si[tid + s];
            if (ov > sv[tid] || (ov == sv[tid] && oi < si[tid])) {
                sv[tid] = ov; si[tid] = oi;
            }
        }
        __syncthreads();
    }

    if (h == 0) {
        int idx1 = si[half << 7];
        float val1 = sv[half << 7];
        int py1 = idx1 / P_;
        int px1 = idx1 - py1 * P_;

        int pxs[K_] = {px0, px1};
        int pys[K_] = {py0, py1};
        float vals[K_] = {val0, val1};
#pragma unroll
        for (int j = 0; j < K_; j++) {
            g_selpx[bc * K_ + j] = pxs[j];
            g_selpy[bc * K_ + j] = pys[j];
            out[OFF_VALS + (c * K_ + j) * B_ + b] = vals[j];
            int o = OFF_OXY + ((c * K_ + j) * B_ + b) * 4;
            out[o + 0] = (float)pxs[j];
            out[o + 1] = (float)(pxs[j] + KER_ - 1);
            out[o + 2] = (float)pys[j];
            out[o + 3] = (float)(pys[j] + KER_ - 1);
        }
    }
    __syncthreads();
    if (tid == 0) g_tick[m] = 0;

    __threadfence();
    cudaTriggerProgrammaticLaunchCompletion();
}

// ===========================================================================
// K3 (PDL consumer of K2): patch gather — proven 2176x256 config, 4 floats
// per thread. Decode runs pre-sync (overlaps K2 drain); selections read
// after cudaGridDependencySynchronize().
// ===========================================================================
__global__ void k_extract(const float* __restrict__ infeat,
                          const float* __restrict__ pesudo,
                          const float* __restrict__ labelT,
                          const float* __restrict__ feat,
                          float* __restrict__ out) {
    int blk = blockIdx.x;
    const float* src;
    int Csrc, ch, c, j, b;
    long base;

    if (blk < 64) {
        int t = blk;
        ch = t & 1;  t >>= 1;
        b  = t & 7;  t >>= 3;
        j  = t & 1;  t >>= 1;
        c  = t;
        src = infeat; Csrc = 2;
        base = OFF_CLS + (long)blk * 1024;
    } else if (blk < 2112) {
        int t = blk - 64;
        int local = t;
        ch = t & 63; t >>= 6;
        b  = t & 7;  t >>= 3;
        j  = t & 1;  t >>= 1;
        c  = t;
        src = feat; Csrc = CDA_;
        base = OFF_FEAT + (long)local * 1024;
    } else if (blk < 2144) {
        int t = blk - 2112;
        int local = t;
        ch = 0;
        b  = t & 7;  t >>= 3;
        j  = t & 1;  t >>= 1;
        c  = t;
        src = pesudo; Csrc = 1;
        base = OFF_PES + (long)local * 1024;
    } else {
        int t = blk - 2144;
        int local = t;
        ch = 0;
        b  = t & 7;  t >>= 3;
        j  = t & 1;  t >>= 1;
        c  = t;
        src = labelT; Csrc = 1;
        base = OFF_TRUE + (long)local * 1024;
    }

    int sel = (b * 2 + c) * K_ + j;

    cudaGridDependencySynchronize();   // wait for K2's selections

    int px = g_selpx[sel];
    int py = g_selpy[sel];

    const float* s = src + (((long)b * Csrc + ch) * H_ + py) * H_ + px;

    int t = threadIdx.x;
    int dy = t >> 3;
    int dx = (t & 7) * 4;
    const float* sp = s + dy * H_ + dx;
    float4 v;
    v.x = sp[0]; v.y = sp[1]; v.z = sp[2]; v.w = sp[3];
    *reinterpret_cast<float4*>(out + base + (long)t * 4) = v;
}

// ---------------------------------------------------------------------------
extern "C" void kernel_launch(void* const* d_in, const int* in_sizes, int n_in,
                              void* d_out, int out_size) {
    const float* infeat  = (const float*)d_in[0];
    const float* pesudo  = (const float*)d_in[1];
    const float* labelT  = (const float*)d_in[2];
    const float* featDA  = (const float*)d_in[3];
    float* out = (float*)d_out;

    k_rowsum<<<512, 256>>>(infeat);

    cudaLaunchAttribute attr[1];
    attr[0].id = cudaLaunchAttributeProgrammaticStreamSerialization;
    attr[0].val.programmaticStreamSerializationAllowed = 1;

    {
        cudaLaunchConfig_t cfg = {};
        cfg.gridDim = dim3(B_, NRB_);
        cfg.blockDim = dim3(256);
        cfg.attrs = attr;
        cfg.numAttrs = 1;
        cudaLaunchKernelEx(&cfg, k_poolsel, out);
    }
    {
        cudaLaunchConfig_t cfg = {};
        cfg.gridDim = dim3(2176);
        cfg.blockDim = dim3(256);
        cfg.attrs = attr;
        cfg.numAttrs = 1;
        cudaLaunchKernelEx(&cfg, k_extract, infeat, pesudo, labelT, featDA, out);
    }
}